// round 14
// baseline (speedup 1.0000x reference)
#include <cuda_runtime.h>
#include <cuda_fp16.h>
#include <cstdint>

#define DB    64
#define NB    65536
#define NK    8192
#define BM    64
#define NCH   64            // K chunks of 128 codes
#define TPB   256

#define STAGE_SZ 16896      // 16KB swizzled B + 512B ce, contiguous in gmem & smem
// smem (bytes): A 8KB @0 | cx 256B @8192 | 2 stages @8448 | cand 4KB @42240
#define SM_CX    8192
#define SM_BST   8448
#define SM_CAND  42240
#define SM_TOT   46336

__device__ __align__(16) char g_eb[(size_t)NCH * STAGE_SZ];  // pre-swizzled B + ce per chunk
__device__ float g_ce[NK];
__device__ float g_partial[1024];

static __device__ __forceinline__ uint32_t smem_u32(const void* p) {
    uint32_t a;
    asm("{ .reg .u64 t; cvta.to.shared.u64 t, %1; cvt.u32.u64 %0, t; }" : "=r"(a) : "l"(p));
    return a;
}

#define CP_ASYNC16(dst, src) asm volatile("cp.async.cg.shared.global [%0], [%1], 16;" :: "r"(dst), "l"(src))
#define CP_COMMIT()          asm volatile("cp.async.commit_group;" ::: "memory")
#define CP_WAITG(n)          asm volatile("cp.async.wait_group %0;" :: "n"(n) : "memory")

#define LDSM_X4(r0, r1, r2, r3, a) \
    asm volatile("ldmatrix.sync.aligned.m8n8.x4.shared.b16 {%0,%1,%2,%3}, [%4];" \
                 : "=r"(r0), "=r"(r1), "=r"(r2), "=r"(r3) : "r"(a))

#define MMA16816(d, a0, a1, a2, a3, b0, b1) \
    asm volatile("mma.sync.aligned.m16n8k16.row.col.f32.f16.f16.f32 " \
                 "{%0,%1,%2,%3}, {%4,%5,%6,%7}, {%8,%9}, {%0,%1,%2,%3};" \
                 : "+f"((d)[0]), "+f"((d)[1]), "+f"((d)[2]), "+f"((d)[3]) \
                 : "r"(a0), "r"(a1), "r"(a2), "r"(a3), "r"(b0), "r"(b1))

// branchless sorted insert of key k into (v1<=v2), all uint32
#define KINS2(k, V1, V2) do {                     \
    uint32_t _k = (k);                            \
    uint32_t _l = min(V1, _k);                    \
    uint32_t _h = max(V1, _k); V1 = _l;           \
    V2 = min(V2, _h);                             \
} while (0)

// ============ codebook -> fp16, PRE-SWIZZLED per-chunk layout ============
__global__ void conv_cb_kernel(const float* __restrict__ cb) {
    size_t i = (size_t)blockIdx.x * blockDim.x + threadIdx.x;  // float4 id (131072)
    float4 v = reinterpret_cast<const float4*>(cb)[i];
    __half2 h0 = __floats2half2_rn(v.x, v.y);
    __half2 h1 = __floats2half2_rn(v.z, v.w);
    uint2 H;
    H.x = *reinterpret_cast<uint32_t*>(&h0);
    H.y = *reinterpret_cast<uint32_t*>(&h1);
    const int code = (int)(i >> 4), fc = (int)(i & 15);
    const int chunk = code >> 7, r = code & 127;
    const int c = fc >> 1, hh = fc & 1;
    const size_t off = (size_t)chunk * STAGE_SZ + r * 128 + ((c ^ (r & 7)) << 4) + hh * 8;
    *reinterpret_cast<uint2*>(g_eb + off) = H;
}

__global__ void ce_kernel(const float* __restrict__ cb) {
    int k = blockIdx.x * blockDim.x + threadIdx.x;
    const float4* p = reinterpret_cast<const float4*>(cb + (size_t)k * DB);
    float s = 0.f;
#pragma unroll
    for (int j = 0; j < 16; j++) {
        float4 v = p[j];
        s += v.x * v.x + v.y * v.y + v.z * v.z + v.w * v.w;
    }
    g_ce[k] = s;
    *reinterpret_cast<float*>(g_eb + (size_t)(k >> 7) * STAGE_SZ + 16384 + (k & 127) * 4) = s;
}

// ====== fused HMMA distance + branchless top-2 + exact rescore + gather + loss ======
// 8 warps = 4 row-groups (16 rows) x 2 code-halves (64 codes). BM=64 rows/CTA.
__global__ void __launch_bounds__(TPB, 4)
argmin_mma_kernel(const float* __restrict__ x, const float* __restrict__ cb,
                  float* __restrict__ out_idx, float* __restrict__ outq) {
    extern __shared__ char smem[];
    const uint32_t sb = smem_u32(smem);
    const int t = threadIdx.x;
    const int wid = t >> 5, lane = t & 31;
    const int mhalf = wid & 3;        // row group: rows mhalf*16 .. +15
    const int chalf = wid >> 2;       // code half: codes chalf*64 .. +63 per chunk

    // stage loader: purely linear copy from pre-swizzled gmem (1056 x 16B)
    auto load_B = [&](int kc, int stage) {
        const char* gsrc = g_eb + (size_t)kc * STAGE_SZ;
        const uint32_t dbase = sb + SM_BST + stage * STAGE_SZ;
#pragma unroll
        for (int i = 0; i < 4; i++) {
            const int id = t + i * TPB;
            CP_ASYNC16(dbase + id * 16, gsrc + id * 16);
        }
        if (t < 32) CP_ASYNC16(dbase + 16384 + t * 16, gsrc + 16384 + t * 16);
    };
    load_B(0, 0); CP_COMMIT();
    load_B(1, 1); CP_COMMIT();

    // A tile: -2x fp16, swizzled 128B rows (64 rows = 1024 float4)
    {
        const float4* xs = reinterpret_cast<const float4*>(x + (size_t)blockIdx.x * BM * DB);
#pragma unroll
        for (int i = 0; i < 4; i++) {
            int id = t + i * TPB;
            int r = id >> 4, fc = id & 15;
            float4 v = xs[id];
            __half2 h0 = __floats2half2_rn(-2.f * v.x, -2.f * v.y);
            __half2 h1 = __floats2half2_rn(-2.f * v.z, -2.f * v.w);
            uint2 H;
            H.x = *reinterpret_cast<uint32_t*>(&h0);
            H.y = *reinterpret_cast<uint32_t*>(&h1);
            int s = fc >> 1, hh = fc & 1;
            *reinterpret_cast<uint2*>(smem + r * 128 + ((s ^ (r & 7)) << 4) + hh * 8) = H;
        }
    }
    // per-row ||x||^2 -> cx smem (4 threads/row)
    {
        const int r = t >> 2, qq = t & 3;
        const float4* xp = reinterpret_cast<const float4*>(
            x + ((size_t)blockIdx.x * BM + r) * DB + qq * 16);
        float s = 0.f;
#pragma unroll
        for (int j = 0; j < 4; j++) {
            float4 v = xp[j];
            s += v.x * v.x + v.y * v.y + v.z * v.z + v.w * v.w;
        }
        s += __shfl_xor_sync(0xffffffffu, s, 1);
        s += __shfl_xor_sync(0xffffffffu, s, 2);
        if (qq == 0) reinterpret_cast<float*>(smem + SM_CX)[r] = s;
    }

    // lane-invariant addressing
    const int RW = mhalf * 16;
    const int rA = RW + ((lane >> 3) & 1) * 8 + (lane & 7);
    const uint32_t aRowBase = sb + rA * 128;
    const int aXor = rA & 7;
    const int akHalf = lane >> 4;
    const int nb_off = ((lane >> 4) & 1) * 8 + (lane & 7);
    const int kb = (lane >> 3) & 1;
    const int nX = nb_off & 7;
    const uint32_t bRow = nb_off * 128;
    const int q = lane & 3;

    __syncthreads();   // cx + A visible
    const float cxa = reinterpret_cast<const float*>(smem + SM_CX)[RW + (lane >> 2)];
    const float cxb = reinterpret_cast<const float*>(smem + SM_CX)[RW + (lane >> 2) + 8];

    // A fragments: chunk-invariant, load once
    uint32_t af[4][4];
#pragma unroll
    for (int kk = 0; kk < 4; kk++)
        LDSM_X4(af[kk][0], af[kk][1], af[kk][2], af[kk][3],
                aRowBase + (((2 * kk + akHalf) ^ aXor) << 4));

    uint32_t va1 = 0xFFFFFFFFu, va2 = 0xFFFFFFFFu;
    uint32_t vb1 = 0xFFFFFFFFu, vb2 = 0xFFFFFFFFu;

    for (int kc = 0; kc < NCH; kc++) {
        const int stage = kc & 1;
        CP_WAITG(1);        // chunk kc's group complete
        __syncthreads();    // everyone's copies visible to everyone

        const uint32_t bBuf = sb + SM_BST + stage * STAGE_SZ;
        const float2* ceS = reinterpret_cast<const float2*>(smem + SM_BST + stage * STAGE_SZ + 16384);
        const uint32_t kcbase = (uint32_t)kc << 4;

#pragma unroll
        for (int g = 0; g < 4; g++) {
            const int nfg = chalf * 8 + 2 * g;           // global 8-code frag pair base
            float2 ce0 = ceS[nfg * 4 + q];
            float2 ce1 = ceS[(nfg + 1) * 4 + q];
            float acc[8];
            acc[0] = ce0.x + cxa; acc[1] = ce0.y + cxa;
            acc[2] = ce0.x + cxb; acc[3] = ce0.y + cxb;
            acc[4] = ce1.x + cxa; acc[5] = ce1.y + cxa;
            acc[6] = ce1.x + cxb; acc[7] = ce1.y + cxb;

            const uint32_t bBase = bBuf + (chalf * 4 + g) * 2048 + bRow;
#pragma unroll
            for (int kk = 0; kk < 4; kk++) {
                uint32_t b0, b1, b2, b3;
                LDSM_X4(b0, b1, b2, b3, bBase + (((2 * kk + kb) ^ nX) << 4));
                MMA16816(&acc[0], af[kk][0], af[kk][1], af[kk][2], af[kk][3], b0, b1);
                MMA16816(&acc[4], af[kk][0], af[kk][1], af[kk][2], af[kk][3], b2, b3);
            }

            // branchless top-2: key = (score_bits & ~0x7FF) | L, L = kc<<4 | g<<2 | s<<1 | p
            const uint32_t L0 = kcbase + (g << 2);
            const uint32_t L1 = L0 + 2;
            uint32_t k0 = (__float_as_uint(acc[0]) & 0xFFFFF800u) | L0;
            uint32_t k1 = (__float_as_uint(acc[1]) & 0xFFFFF800u) | (L0 + 1);
            uint32_t k2 = (__float_as_uint(acc[2]) & 0xFFFFF800u) | L0;
            uint32_t k3 = (__float_as_uint(acc[3]) & 0xFFFFF800u) | (L0 + 1);
            uint32_t k4 = (__float_as_uint(acc[4]) & 0xFFFFF800u) | L1;
            uint32_t k5 = (__float_as_uint(acc[5]) & 0xFFFFF800u) | (L1 + 1);
            uint32_t k6 = (__float_as_uint(acc[6]) & 0xFFFFF800u) | L1;
            uint32_t k7 = (__float_as_uint(acc[7]) & 0xFFFFF800u) | (L1 + 1);
            KINS2(k0, va1, va2);
            KINS2(k1, va1, va2);
            KINS2(k2, vb1, vb2);
            KINS2(k3, vb1, vb2);
            KINS2(k4, va1, va2);
            KINS2(k5, va1, va2);
            KINS2(k6, vb1, vb2);
            KINS2(k7, vb1, vb2);
        }

        __syncthreads();    // all warps done reading this stage before refill (WAR)
        if (kc + 2 < NCH) load_B(kc + 2, stage);
        CP_COMMIT();        // unconditional: uniform group count
    }

    // decode keys -> codes, dump 16 candidates/row (2 per lane x 2 code-half warps x 4 quad lanes)
    {
        int* cand = reinterpret_cast<int*>(smem + SM_CAND);
        const int ra = RW + (lane >> 2), rb = ra + 8;
        const int slot = chalf * 8 + q * 2;
        uint32_t ka[2] = {va1, va2};
        uint32_t kbv[2] = {vb1, vb2};
#pragma unroll
        for (int j = 0; j < 2; j++) {
            uint32_t La = ka[j] & 0x7FFu;
            uint32_t Lb = kbv[j] & 0x7FFu;
            cand[ra * 16 + slot + j] =
                (int)(((La >> 4) << 7) | (chalf << 6) | (((La >> 2) & 3) << 4) |
                      (((La >> 1) & 1) << 3) | (q << 1) | (La & 1));
            cand[rb * 16 + slot + j] =
                (int)(((Lb >> 4) << 7) | (chalf << 6) | (((Lb >> 2) & 3) << 4) |
                      (((Lb >> 1) & 1) << 3) | (q << 1) | (Lb & 1));
        }
    }
    __syncthreads();

    // exact fp32 rescore + gather + loss: 4 threads/row, 16 dims each, 16 candidates
    float lloss = 0.f;
    {
        const int* cand = reinterpret_cast<const int*>(smem + SM_CAND);
        const int quarter = t & 3;
        const int r = t >> 2;
        float xr[16];
        const float4* xp = reinterpret_cast<const float4*>(
            x + ((size_t)blockIdx.x * BM + r) * DB + quarter * 16);
#pragma unroll
        for (int j = 0; j < 4; j++) {
            float4 v = xp[j];
            xr[j * 4] = v.x; xr[j * 4 + 1] = v.y; xr[j * 4 + 2] = v.z; xr[j * 4 + 3] = v.w;
        }
        float best = 3.4e38f;
        int bi = NK;
#pragma unroll 1
        for (int j = 0; j < 16; j++) {
            const int c = cand[r * 16 + j];
            const float4* ep = reinterpret_cast<const float4*>(cb + (size_t)c * DB + quarter * 16);
            float dot = 0.f;
#pragma unroll
            for (int u = 0; u < 4; u++) {
                float4 e = ep[u];
                dot += xr[u * 4] * e.x + xr[u * 4 + 1] * e.y + xr[u * 4 + 2] * e.z + xr[u * 4 + 3] * e.w;
            }
            dot += __shfl_xor_sync(0xffffffffu, dot, 1);
            dot += __shfl_xor_sync(0xffffffffu, dot, 2);
            const float score = fmaf(-2.f, dot, g_ce[c]);
            if (score < best || (score == best && c < bi)) { best = score; bi = c; }
        }
        if (quarter == 0) out_idx[(size_t)blockIdx.x * BM + r] = (float)bi;

        // gather best row into outq + local loss partial
        const float4* bp = reinterpret_cast<const float4*>(cb + (size_t)bi * DB + quarter * 16);
        float4* o = reinterpret_cast<float4*>(outq + ((size_t)blockIdx.x * BM + r) * DB + quarter * 16);
#pragma unroll
        for (int u = 0; u < 4; u++) {
            float4 e = bp[u];
            o[u] = e;
            float d0 = xr[u * 4] - e.x, d1 = xr[u * 4 + 1] - e.y;
            float d2 = xr[u * 4 + 2] - e.z, d3 = xr[u * 4 + 3] - e.w;
            lloss += d0 * d0 + d1 * d1 + d2 * d2 + d3 * d3;
        }
    }
    __syncthreads();   // cand reads done; reuse A region for reduction
    {
        float* rs = reinterpret_cast<float*>(smem);
        rs[t] = lloss;
        __syncthreads();
        for (int off = 128; off > 0; off >>= 1) {
            if (t < off) rs[t] += rs[t + off];
            __syncthreads();
        }
        if (t == 0) g_partial[blockIdx.x] = rs[0];
    }
}

__global__ void loss_finalize_kernel(float* __restrict__ out_loss, int nparts, float scale) {
    __shared__ float rs[256];
    int t = threadIdx.x;
    float s = 0.f;
    for (int i = t; i < nparts; i += 256) s += g_partial[i];
    rs[t] = s;
    __syncthreads();
    for (int off = 128; off > 0; off >>= 1) {
        if (t < off) rs[t] += rs[t + off];
        __syncthreads();
    }
    if (t == 0) out_loss[0] = rs[0] * scale;
}

extern "C" void kernel_launch(void* const* d_in, const int* in_sizes, int n_in,
                              void* d_out, int out_size) {
    const float* x  = (const float*)d_in[0];
    const float* cb = (const float*)d_in[1];
    const int B = in_sizes[0] / DB;   // 65536
    (void)n_in; (void)out_size;

    float* out      = (float*)d_out;
    float* out_q    = out;
    float* out_loss = out + (size_t)B * DB;
    float* out_idx  = out_loss + 1;

    conv_cb_kernel<<<(NK * 16) / 256, 256>>>(cb);
    ce_kernel<<<NK / 256, 256>>>(cb);

    cudaFuncSetAttribute(argmin_mma_kernel, cudaFuncAttributeMaxDynamicSharedMemorySize, SM_TOT);
    argmin_mma_kernel<<<B / BM, TPB, SM_TOT>>>(x, cb, out_idx, out_q);

    loss_finalize_kernel<<<1, 256>>>(out_loss, B / BM, 1.25f / ((float)B * DB));
}

// round 17
// speedup vs baseline: 1.1463x; 1.1463x over previous
#include <cuda_runtime.h>
#include <cuda_fp16.h>
#include <cstdint>

#define DB    64
#define NB    65536
#define NK    8192
#define BM    128
#define NCHH  32            // chunks per half (codebook split in 2)
#define TPB   256

#define STAGE_SZ 16896      // 16KB swizzled B + 512B ce, contiguous in gmem & smem
// smem (bytes): A 16KB @0 | cx 512B @16384 | 2 stages @16896 | cand 4KB @50688
#define SM_CX    16384
#define SM_BST   16896
#define SM_CAND  50688
#define SM_TOT   54784

__device__ __align__(16) char g_eb[(size_t)(2 * NCHH) * STAGE_SZ];  // pre-swizzled B + ce per chunk
__device__ float g_ce[NK];
__device__ float g_bs[2 * NB];     // per-half exact best score
__device__ int   g_bi[2 * NB];     // per-half exact best index
__device__ float g_partial[1024];

static __device__ __forceinline__ uint32_t smem_u32(const void* p) {
    uint32_t a;
    asm("{ .reg .u64 t; cvta.to.shared.u64 t, %1; cvt.u32.u64 %0, t; }" : "=r"(a) : "l"(p));
    return a;
}

#define CP_ASYNC16(dst, src) asm volatile("cp.async.cg.shared.global [%0], [%1], 16;" :: "r"(dst), "l"(src))
#define CP_COMMIT()          asm volatile("cp.async.commit_group;" ::: "memory")
#define CP_WAITG(n)          asm volatile("cp.async.wait_group %0;" :: "n"(n) : "memory")

#define LDSM_X4(r0, r1, r2, r3, a) \
    asm volatile("ldmatrix.sync.aligned.m8n8.x4.shared.b16 {%0,%1,%2,%3}, [%4];" \
                 : "=r"(r0), "=r"(r1), "=r"(r2), "=r"(r3) : "r"(a))

#define MMA16816(d, a0, a1, a2, a3, b0, b1) \
    asm volatile("mma.sync.aligned.m16n8k16.row.col.f32.f16.f16.f32 " \
                 "{%0,%1,%2,%3}, {%4,%5,%6,%7}, {%8,%9}, {%0,%1,%2,%3};" \
                 : "+f"((d)[0]), "+f"((d)[1]), "+f"((d)[2]), "+f"((d)[3]) \
                 : "r"(a0), "r"(a1), "r"(a2), "r"(a3), "r"(b0), "r"(b1))

// branchless sorted insert of key k into (v1<=v2), all uint32
#define KINS2(k, V1, V2) do {                     \
    uint32_t _k = (k);                            \
    uint32_t _l = min(V1, _k);                    \
    uint32_t _h = max(V1, _k); V1 = _l;           \
    V2 = min(V2, _h);                             \
} while (0)

// ============ fused codebook prep: fp16 pre-swizzled pack + ||e||^2 ============
__global__ void prep_cb_kernel(const float* __restrict__ cb) {
    const int k = blockIdx.x * blockDim.x + threadIdx.x;   // code id (8192)
    const float4* p = reinterpret_cast<const float4*>(cb + (size_t)k * DB);
    const int chunk = k >> 7, r = k & 127;
    char* dst = g_eb + (size_t)chunk * STAGE_SZ + r * 128;
    float s = 0.f;
#pragma unroll
    for (int fc = 0; fc < 16; fc++) {
        float4 v = p[fc];
        s += v.x * v.x + v.y * v.y + v.z * v.z + v.w * v.w;
        __half2 h0 = __floats2half2_rn(v.x, v.y);
        __half2 h1 = __floats2half2_rn(v.z, v.w);
        uint2 H;
        H.x = *reinterpret_cast<uint32_t*>(&h0);
        H.y = *reinterpret_cast<uint32_t*>(&h1);
        const int c = fc >> 1, hh = fc & 1;
        *reinterpret_cast<uint2*>(dst + (((c ^ (r & 7)) << 4) + hh * 8)) = H;
    }
    g_ce[k] = s;
    *reinterpret_cast<float*>(g_eb + (size_t)chunk * STAGE_SZ + 16384 + r * 4) = s;
}

// ====== fused HMMA distance + branchless top-2 + exact per-half rescore ======
// grid = 1024: rb = blockIdx.x & 511 (row block), half = blockIdx.x >> 9 (code half)
__global__ void __launch_bounds__(TPB, 4)
argmin_mma_kernel(const float* __restrict__ x, const float* __restrict__ cb) {
    extern __shared__ char smem[];
    const uint32_t sb = smem_u32(smem);
    const int t = threadIdx.x;
    const int wid = t >> 5, lane = t & 31;
    const int rb = blockIdx.x & 511;
    const int half = blockIdx.x >> 9;
    const int cbase = half << 12;             // first code of this half

    // stage loader: purely linear copy from pre-swizzled gmem (1056 x 16B)
    auto load_B = [&](int kc, int stage) {
        const char* gsrc = g_eb + (size_t)(half * NCHH + kc) * STAGE_SZ;
        const uint32_t dbase = sb + SM_BST + stage * STAGE_SZ;
#pragma unroll
        for (int i = 0; i < 4; i++) {
            const int id = t + i * TPB;
            CP_ASYNC16(dbase + id * 16, gsrc + id * 16);
        }
        if (t < 32) CP_ASYNC16(dbase + 16384 + t * 16, gsrc + 16384 + t * 16);
    };
    load_B(0, 0); CP_COMMIT();
    load_B(1, 1); CP_COMMIT();

    // A tile: -2x fp16, swizzled 128B rows
    {
        const float4* xs = reinterpret_cast<const float4*>(x + (size_t)rb * BM * DB);
#pragma unroll
        for (int i = 0; i < 8; i++) {
            int id = t + i * TPB;          // 2048 float4
            int r = id >> 4, fc = id & 15;
            float4 v = xs[id];
            __half2 h0 = __floats2half2_rn(-2.f * v.x, -2.f * v.y);
            __half2 h1 = __floats2half2_rn(-2.f * v.z, -2.f * v.w);
            uint2 H;
            H.x = *reinterpret_cast<uint32_t*>(&h0);
            H.y = *reinterpret_cast<uint32_t*>(&h1);
            int s = fc >> 1, hh = fc & 1;
            *reinterpret_cast<uint2*>(smem + r * 128 + ((s ^ (r & 7)) << 4) + hh * 8) = H;
        }
    }
    // per-row ||x||^2 -> cx smem (2 threads/row)
    {
        const int r = t >> 1, hf = t & 1;
        const float4* xp = reinterpret_cast<const float4*>(
            x + ((size_t)rb * BM + r) * DB + hf * 32);
        float s = 0.f;
#pragma unroll
        for (int j = 0; j < 8; j++) {
            float4 v = xp[j];
            s += v.x * v.x + v.y * v.y + v.z * v.z + v.w * v.w;
        }
        s += __shfl_xor_sync(0xffffffffu, s, 1);
        if (hf == 0) reinterpret_cast<float*>(smem + SM_CX)[r] = s;
    }

    // lane-invariant addressing (validated pattern)
    const int RW = wid * 16;
    const int rA = RW + ((lane >> 3) & 1) * 8 + (lane & 7);
    const uint32_t aRowBase = sb + rA * 128;
    const int aXor = rA & 7;
    const int akHalf = lane >> 4;
    const int nb_off = ((lane >> 4) & 1) * 8 + (lane & 7);
    const int kb = (lane >> 3) & 1;
    const int nX = nb_off & 7;
    const uint32_t bRow = nb_off * 128;
    const int q = lane & 3;

    __syncthreads();   // cx + A visible
    const float cxa = reinterpret_cast<const float*>(smem + SM_CX)[RW + (lane >> 2)];
    const float cxb = reinterpret_cast<const float*>(smem + SM_CX)[RW + (lane >> 2) + 8];

    // A fragments: chunk-invariant, load once
    uint32_t af[4][4];
#pragma unroll
    for (int kk = 0; kk < 4; kk++)
        LDSM_X4(af[kk][0], af[kk][1], af[kk][2], af[kk][3],
                aRowBase + (((2 * kk + akHalf) ^ aXor) << 4));

    uint32_t va1 = 0xFFFFFFFFu, va2 = 0xFFFFFFFFu;
    uint32_t vb1 = 0xFFFFFFFFu, vb2 = 0xFFFFFFFFu;

    for (int kc = 0; kc < NCHH; kc++) {
        const int stage = kc & 1;
        CP_WAITG(1);        // chunk kc's group complete
        __syncthreads();    // everyone's copies visible to everyone

        const uint32_t bBuf = sb + SM_BST + stage * STAGE_SZ;
        const float2* ceS = reinterpret_cast<const float2*>(smem + SM_BST + stage * STAGE_SZ + 16384);
        const uint32_t kcbase = (uint32_t)kc << 5;

#pragma unroll
        for (int g = 0; g < 8; g++) {
            float2 ce0 = ceS[(2 * g) * 4 + q];
            float2 ce1 = ceS[(2 * g + 1) * 4 + q];
            float acc[8];
            acc[0] = ce0.x + cxa; acc[1] = ce0.y + cxa;
            acc[2] = ce0.x + cxb; acc[3] = ce0.y + cxb;
            acc[4] = ce1.x + cxa; acc[5] = ce1.y + cxa;
            acc[6] = ce1.x + cxb; acc[7] = ce1.y + cxb;

#pragma unroll
            for (int kk = 0; kk < 4; kk++) {
                uint32_t b0, b1, b2, b3;
                LDSM_X4(b0, b1, b2, b3, bBuf + g * 2048 + bRow + (((2 * kk + kb) ^ nX) << 4));
                MMA16816(&acc[0], af[kk][0], af[kk][1], af[kk][2], af[kk][3], b0, b1);
                MMA16816(&acc[4], af[kk][0], af[kk][1], af[kk][2], af[kk][3], b2, b3);
            }

            // branchless top-2: key = (score_bits & ~0x7FF) | L, L = kc<<5 | nf<<1 | p
            const uint32_t L0 = kcbase + ((2 * g) << 1);
            const uint32_t L1 = kcbase + ((2 * g + 1) << 1);
            uint32_t k0 = (__float_as_uint(acc[0]) & 0xFFFFF800u) | L0;
            uint32_t k1 = (__float_as_uint(acc[1]) & 0xFFFFF800u) | (L0 + 1);
            uint32_t k2 = (__float_as_uint(acc[2]) & 0xFFFFF800u) | L0;
            uint32_t k3 = (__float_as_uint(acc[3]) & 0xFFFFF800u) | (L0 + 1);
            uint32_t k4 = (__float_as_uint(acc[4]) & 0xFFFFF800u) | L1;
            uint32_t k5 = (__float_as_uint(acc[5]) & 0xFFFFF800u) | (L1 + 1);
            uint32_t k6 = (__float_as_uint(acc[6]) & 0xFFFFF800u) | L1;
            uint32_t k7 = (__float_as_uint(acc[7]) & 0xFFFFF800u) | (L1 + 1);
            KINS2(k0, va1, va2);
            KINS2(k1, va1, va2);
            KINS2(k2, vb1, vb2);
            KINS2(k3, vb1, vb2);
            KINS2(k4, va1, va2);
            KINS2(k5, va1, va2);
            KINS2(k6, vb1, vb2);
            KINS2(k7, vb1, vb2);
        }

        __syncthreads();    // all warps done reading this stage before refill (WAR)
        if (kc + 2 < NCHH) load_B(kc + 2, stage);
        CP_COMMIT();        // unconditional: uniform group count
    }

    // decode keys -> codes within this half, dump 8 candidates/row
    {
        int* cand = reinterpret_cast<int*>(smem + SM_CAND);
        const int ra = RW + (lane >> 2), rbv = ra + 8;
        uint32_t ka[2] = {va1, va2};
        uint32_t kbv2[2] = {vb1, vb2};
#pragma unroll
        for (int j = 0; j < 2; j++) {
            uint32_t La = ka[j] & 0x7FFu;
            uint32_t Lb = kbv2[j] & 0x7FFu;
            cand[ra * 8 + q * 2 + j] = cbase +
                (int)(((La >> 5) << 7) | (((La >> 1) & 15) << 3) | (q << 1) | (La & 1));
            cand[rbv * 8 + q * 2 + j] = cbase +
                (int)(((Lb >> 5) << 7) | (((Lb >> 1) & 15) << 3) | (q << 1) | (Lb & 1));
        }
    }
    __syncthreads();

    // exact fp32 rescore over own half's 8 candidates -> per-half (score, idx) to gmem
    {
        const int* cand = reinterpret_cast<const int*>(smem + SM_CAND);
        const int quarter = t & 3;
#pragma unroll 1
        for (int it = 0; it < 2; it++) {
            const int r = (t >> 2) + it * 64;
            float xr[16];
            const float4* xp = reinterpret_cast<const float4*>(
                x + ((size_t)rb * BM + r) * DB + quarter * 16);
#pragma unroll
            for (int j = 0; j < 4; j++) {
                float4 v = xp[j];
                xr[j * 4] = v.x; xr[j * 4 + 1] = v.y; xr[j * 4 + 2] = v.z; xr[j * 4 + 3] = v.w;
            }
            float best = 3.4e38f;
            int bi = NK;
#pragma unroll 1
            for (int j = 0; j < 8; j++) {
                const int c = cand[r * 8 + j];
                const float4* ep = reinterpret_cast<const float4*>(cb + (size_t)c * DB + quarter * 16);
                float dot = 0.f;
#pragma unroll
                for (int u = 0; u < 4; u++) {
                    float4 e = ep[u];
                    dot += xr[u * 4] * e.x + xr[u * 4 + 1] * e.y + xr[u * 4 + 2] * e.z + xr[u * 4 + 3] * e.w;
                }
                dot += __shfl_xor_sync(0xffffffffu, dot, 1);
                dot += __shfl_xor_sync(0xffffffffu, dot, 2);
                const float score = fmaf(-2.f, dot, g_ce[c]);
                if (score < best || (score == best && c < bi)) { best = score; bi = c; }
            }
            if (quarter == 0) {
                const size_t row = (size_t)rb * BM + r;
                g_bs[half * NB + row] = best;
                g_bi[half * NB + row] = bi;
            }
        }
    }
}

// ============ merge halves + gather + loss ============
__global__ void merge_gather_loss(const float* __restrict__ x, const float* __restrict__ cb,
                                  float* __restrict__ out_idx, float* __restrict__ outq) {
    __shared__ float rs[256];
    const int t = threadIdx.x;
    const int rl = t >> 2, seg = t & 3;
    const size_t row = (size_t)blockIdx.x * 64 + rl;
    const float s0 = g_bs[row], s1 = g_bs[NB + row];
    const int k = (s1 < s0) ? g_bi[NB + row] : g_bi[row];   // tie -> half0 (lower idx)

    const float4* qv = reinterpret_cast<const float4*>(cb + (size_t)k * DB + seg * 16);
    const float4* xi = reinterpret_cast<const float4*>(x + row * DB + seg * 16);
    float4* o = reinterpret_cast<float4*>(outq + row * DB + seg * 16);
    float s = 0.f;
#pragma unroll
    for (int j = 0; j < 4; j++) {
        float4 e = qv[j], xv = xi[j];
        o[j] = e;
        float dx = xv.x - e.x, dy = xv.y - e.y, dz = xv.z - e.z, dw = xv.w - e.w;
        s += dx * dx + dy * dy + dz * dz + dw * dw;
    }
    if (seg == 0) out_idx[row] = (float)k;

    rs[t] = s;
    __syncthreads();
    for (int off = 128; off > 0; off >>= 1) {
        if (t < off) rs[t] += rs[t + off];
        __syncthreads();
    }
    if (t == 0) g_partial[blockIdx.x] = rs[0];
}

__global__ void loss_finalize_kernel(float* __restrict__ out_loss, int nparts, float scale) {
    __shared__ float rs[256];
    int t = threadIdx.x;
    float s = 0.f;
    for (int i = t; i < nparts; i += 256) s += g_partial[i];
    rs[t] = s;
    __syncthreads();
    for (int off = 128; off > 0; off >>= 1) {
        if (t < off) rs[t] += rs[t + off];
        __syncthreads();
    }
    if (t == 0) out_loss[0] = rs[0] * scale;
}

extern "C" void kernel_launch(void* const* d_in, const int* in_sizes, int n_in,
                              void* d_out, int out_size) {
    const float* x  = (const float*)d_in[0];
    const float* cb = (const float*)d_in[1];
    const int B = in_sizes[0] / DB;   // 65536
    (void)n_in; (void)out_size;

    float* out      = (float*)d_out;
    float* out_q    = out;
    float* out_loss = out + (size_t)B * DB;
    float* out_idx  = out_loss + 1;

    prep_cb_kernel<<<NK / 256, 256>>>(cb);

    cudaFuncSetAttribute(argmin_mma_kernel, cudaFuncAttributeMaxDynamicSharedMemorySize, SM_TOT);
    argmin_mma_kernel<<<(B / BM) * 2, TPB, SM_TOT>>>(x, cb);

    merge_gather_loss<<<B / 64, 256>>>(x, cb, out_idx, out_q);
    loss_finalize_kernel<<<1, 256>>>(out_loss, B / 64, 1.25f / ((float)B * DB));
}